// round 1
// baseline (speedup 1.0000x reference)
#include <cuda_runtime.h>

#define T_TOK   16384
#define DIM     2048
#define NEXP    64
#define NB      4
#define SEQ     4096
#define BM      64
#define BK      16
#define NTHREADS 128
#define ROW     68          // padded smem row (floats) for 64-wide tiles

__device__ float        g_score_sum[NB * NEXP];
__device__ unsigned int g_counts[NB * NEXP];

__global__ void zero_aux_kernel() {
    int i = threadIdx.x;
    if (i < NB * NEXP) {
        g_score_sum[i] = 0.0f;
        g_counts[i] = 0u;
    }
}

__device__ __forceinline__ unsigned long long pack_dup(float x) {
    unsigned long long r;
    asm("mov.b64 %0, {%1, %1};" : "=l"(r) : "f"(x));
    return r;
}

__device__ __forceinline__ void fma2(unsigned long long& d,
                                     unsigned long long a,
                                     unsigned long long b) {
    asm("fma.rn.f32x2 %0, %1, %2, %0;" : "+l"(d) : "l"(a), "l"(b));
}

__device__ __forceinline__ void unpack2(unsigned long long v, float& lo, float& hi) {
    asm("mov.b64 {%0, %1}, %2;" : "=f"(lo), "=f"(hi) : "l"(v));
}

__global__ __launch_bounds__(NTHREADS)
void moe_gate_kernel(const float* __restrict__ X,
                     const float* __restrict__ W,
                     float* __restrict__ out)
{
    // smem: during GEMM, As = sm[0 .. BK*ROW), Bs = sm[BK*ROW .. 2*BK*ROW)
    // after GEMM, sm[0 .. BM*ROW) holds logits/scores [token][expert] (row=ROW)
    __shared__ float sm[BM * ROW];
    __shared__ unsigned int cnt[NEXP];

    float* As = sm;
    float* Bs = sm + BK * ROW;

    const int tid = threadIdx.x;
    const int ty  = tid & 15;   // token group: tokens ty*4 .. ty*4+3
    const int tx  = tid >> 4;   // expert group: experts tx*8 .. tx*8+7
    const int tok0 = blockIdx.x * BM;
    const float* Xb = X + (size_t)tok0 * DIM;

    unsigned long long acc[4][4];
#pragma unroll
    for (int i = 0; i < 4; i++)
#pragma unroll
        for (int p = 0; p < 4; p++)
            acc[i][p] = 0ull;

    for (int kt = 0; kt < DIM / BK; kt++) {
        // ---- load X tile: 64 tokens x 16 k  ->  As[k][token] (transposed) ----
#pragma unroll
        for (int s = tid; s < 256; s += NTHREADS) {
            int row = s >> 2;            // token (or expert below)
            int kk  = (s & 3) * 4;
            float4 v = *(const float4*)&Xb[(size_t)row * DIM + kt * BK + kk];
            As[(kk + 0) * ROW + row] = v.x;
            As[(kk + 1) * ROW + row] = v.y;
            As[(kk + 2) * ROW + row] = v.z;
            As[(kk + 3) * ROW + row] = v.w;
        }
        // ---- load W tile: 64 experts x 16 k -> Bs[k][expert] ----
#pragma unroll
        for (int s = tid; s < 256; s += NTHREADS) {
            int row = s >> 2;
            int kk  = (s & 3) * 4;
            float4 v = *(const float4*)&W[(size_t)row * DIM + kt * BK + kk];
            Bs[(kk + 0) * ROW + row] = v.x;
            Bs[(kk + 1) * ROW + row] = v.y;
            Bs[(kk + 2) * ROW + row] = v.z;
            Bs[(kk + 3) * ROW + row] = v.w;
        }
        __syncthreads();

#pragma unroll
        for (int k = 0; k < BK; k++) {
            float4 av = *(const float4*)&As[k * ROW + ty * 4];
            unsigned long long ap[4];
            ap[0] = pack_dup(av.x);
            ap[1] = pack_dup(av.y);
            ap[2] = pack_dup(av.z);
            ap[3] = pack_dup(av.w);

            const ulonglong2 b01 = *(const ulonglong2*)&Bs[k * ROW + tx * 8];
            const ulonglong2 b23 = *(const ulonglong2*)&Bs[k * ROW + tx * 8 + 4];
            unsigned long long bb[4] = { b01.x, b01.y, b23.x, b23.y };

#pragma unroll
            for (int i = 0; i < 4; i++)
#pragma unroll
                for (int p = 0; p < 4; p++)
                    fma2(acc[i][p], ap[i], bb[p]);
        }
        __syncthreads();
    }

    // ---- write logits to smem: [token][expert], row stride ROW ----
#pragma unroll
    for (int i = 0; i < 4; i++) {
        int token = ty * 4 + i;
#pragma unroll
        for (int p = 0; p < 4; p++) {
            float lo, hi;
            unpack2(acc[i][p], lo, hi);
            sm[token * ROW + tx * 8 + 2 * p]     = lo;
            sm[token * ROW + tx * 8 + 2 * p + 1] = hi;
        }
    }
    if (tid < NEXP) cnt[tid] = 0u;
    __syncthreads();

    // ---- per-token softmax + top-2 (one thread per token) ----
    if (tid < BM) {
        float* row = &sm[tid * ROW];
        float mx = row[0];
#pragma unroll
        for (int e = 1; e < NEXP; e++) mx = fmaxf(mx, row[e]);
        float sum = 0.0f;
#pragma unroll
        for (int e = 0; e < NEXP; e++) {
            float p = expf(row[e] - mx);
            row[e] = p;
            sum += p;
        }
        float inv = 1.0f / sum;
        float v1 = -1.0f, v2 = -1.0f;
        int i1 = 0, i2 = 0;
#pragma unroll
        for (int e = 0; e < NEXP; e++) {
            float p = row[e] * inv;
            row[e] = p;                     // store softmax score (for aux sums)
            if (p > v1) { v2 = v1; i2 = i1; v1 = p; i1 = e; }
            else if (p > v2) { v2 = p; i2 = e; }
        }
        float tot = v1 + v2 + 1e-20f;
        float s1 = v1 / tot;
        float s2 = v2 / tot;

        int gt = tok0 + tid;
        // output layout: [idx (2T floats)] [scores (2T floats)] [aux (1)]
        out[2 * gt + 0] = (float)i1;
        out[2 * gt + 1] = (float)i2;
        out[2 * T_TOK + 2 * gt + 0] = s1;
        out[2 * T_TOK + 2 * gt + 1] = s2;

        atomicAdd(&cnt[i1], 1u);
        atomicAdd(&cnt[i2], 1u);
    }
    __syncthreads();

    // ---- per-expert column sums of softmax scores + count flush ----
    if (tid < NEXP) {
        int e = tid;
        float cs = 0.0f;
#pragma unroll
        for (int t = 0; t < BM; t++) cs += sm[t * ROW + e];
        int b = tok0 / SEQ;
        atomicAdd(&g_score_sum[b * NEXP + e], cs);
        atomicAdd(&g_counts[b * NEXP + e], cnt[e]);
    }
}

__global__ void finalize_aux_kernel(float* __restrict__ out_aux) {
    __shared__ float red[NB * NEXP];
    int i = threadIdx.x;   // 256 threads = NB*NEXP
    float v = (float)g_counts[i] * ((float)NEXP / (float)(SEQ * 2))
              * (g_score_sum[i] / (float)SEQ);
    red[i] = v;
    __syncthreads();
    for (int s = (NB * NEXP) / 2; s > 0; s >>= 1) {
        if (i < s) red[i] += red[i + s];
        __syncthreads();
    }
    if (i == 0) out_aux[0] = red[0] * (0.1f / (float)NB);
}

extern "C" void kernel_launch(void* const* d_in, const int* in_sizes, int n_in,
                              void* d_out, int out_size) {
    const float* X = (const float*)d_in[0];   // [4,4096,2048] f32
    const float* W = (const float*)d_in[1];   // [64,2048] f32
    float* out = (float*)d_out;

    zero_aux_kernel<<<1, 256>>>();
    moe_gate_kernel<<<T_TOK / BM, NTHREADS>>>(X, W, out);
    finalize_aux_kernel<<<1, 256>>>(out + 4 * T_TOK);
}

// round 2
// speedup vs baseline: 1.1164x; 1.1164x over previous
#include <cuda_runtime.h>

#define T_TOK   16384
#define DIM     2048
#define NEXP    64
#define NB      4
#define SEQ     4096
#define BM      64
#define BK      32
#define NTILES  (DIM / BK)     // 64
#define NTHREADS 128
#define ROW     68             // padded smem row (floats)

__device__ float        g_score_sum[NB * NEXP];   // zero-initialized at module load
__device__ unsigned int g_counts[NB * NEXP];      // finalize kernel re-zeros each call

__device__ __forceinline__ unsigned long long pack_dup(float x) {
    unsigned long long r;
    asm("mov.b64 %0, {%1, %1};" : "=l"(r) : "f"(x));
    return r;
}

__device__ __forceinline__ void fma2(unsigned long long& d,
                                     unsigned long long a,
                                     unsigned long long b) {
    asm("fma.rn.f32x2 %0, %1, %2, %0;" : "+l"(d) : "l"(a), "l"(b));
}

__device__ __forceinline__ void unpack2(unsigned long long v, float& lo, float& hi) {
    asm("mov.b64 {%0, %1}, %2;" : "=f"(lo), "=f"(hi) : "l"(v));
}

__global__ __launch_bounds__(NTHREADS, 2)
void moe_gate_kernel(const float* __restrict__ X,
                     const float* __restrict__ W,
                     float* __restrict__ out)
{
    // Two stages, each stage = As[BK][ROW] + Bs[BK][ROW].
    // After the GEMM, the front of sm is reused for logits [BM][ROW].
    __shared__ float sm[2 * 2 * BK * ROW];
    __shared__ unsigned int cnt[NEXP];

    const int tid = threadIdx.x;
    const int ty  = tid & 15;    // token group (4 tokens)
    const int tx  = tid >> 4;    // expert group (8 experts)
    const int tok0 = blockIdx.x * BM;
    const float* Xb = X + (size_t)tok0 * DIM;

    // Per-thread load geometry: kk fixed, 4 rows at stride 16
    const int kk    = (tid & 7) * 4;
    const int rbase = tid >> 3;          // 0..15

    unsigned long long acc[4][4];
#pragma unroll
    for (int i = 0; i < 4; i++)
#pragma unroll
        for (int p = 0; p < 4; p++)
            acc[i][p] = 0ull;

    float4 ra[4], rb[4];

    // ---- prolog: load tile 0 ----
#pragma unroll
    for (int i = 0; i < 4; i++) {
        int row = rbase + 16 * i;
        ra[i] = *(const float4*)&Xb[(size_t)row * DIM + kk];
        rb[i] = *(const float4*)&W [(size_t)row * DIM + kk];
    }
    {
        float* As = sm;
        float* Bs = sm + BK * ROW;
#pragma unroll
        for (int i = 0; i < 4; i++) {
            int row = rbase + 16 * i;
            As[(kk + 0) * ROW + row] = ra[i].x;
            As[(kk + 1) * ROW + row] = ra[i].y;
            As[(kk + 2) * ROW + row] = ra[i].z;
            As[(kk + 3) * ROW + row] = ra[i].w;
            Bs[(kk + 0) * ROW + row] = rb[i].x;
            Bs[(kk + 1) * ROW + row] = rb[i].y;
            Bs[(kk + 2) * ROW + row] = rb[i].z;
            Bs[(kk + 3) * ROW + row] = rb[i].w;
        }
    }
    __syncthreads();

    int cur = 0;
    for (int kt = 0; kt < NTILES; kt++) {
        // ---- issue LDGs for next tile early (latency hidden by compute) ----
        if (kt + 1 < NTILES) {
            int k0 = (kt + 1) * BK;
#pragma unroll
            for (int i = 0; i < 4; i++) {
                int row = rbase + 16 * i;
                ra[i] = *(const float4*)&Xb[(size_t)row * DIM + k0 + kk];
                rb[i] = *(const float4*)&W [(size_t)row * DIM + k0 + kk];
            }
        }

        // ---- compute on current stage ----
        const float* As = sm + cur * (2 * BK * ROW);
        const float* Bs = As + BK * ROW;
#pragma unroll 8
        for (int k = 0; k < BK; k++) {
            const float* Ak = As + k * ROW;
            const float* Bk = Bs + k * ROW;
            float4 av = *(const float4*)&Ak[ty * 4];
            unsigned long long ap[4];
            ap[0] = pack_dup(av.x);
            ap[1] = pack_dup(av.y);
            ap[2] = pack_dup(av.z);
            ap[3] = pack_dup(av.w);

            const ulonglong2 b01 = *(const ulonglong2*)&Bk[tx * 8];
            const ulonglong2 b23 = *(const ulonglong2*)&Bk[tx * 8 + 4];
            unsigned long long bb[4] = { b01.x, b01.y, b23.x, b23.y };

#pragma unroll
            for (int i = 0; i < 4; i++)
#pragma unroll
                for (int p = 0; p < 4; p++)
                    fma2(acc[i][p], ap[i], bb[p]);
        }

        // ---- store next tile into the other stage ----
        if (kt + 1 < NTILES) {
            float* Asn = sm + (cur ^ 1) * (2 * BK * ROW);
            float* Bsn = Asn + BK * ROW;
#pragma unroll
            for (int i = 0; i < 4; i++) {
                int row = rbase + 16 * i;
                Asn[(kk + 0) * ROW + row] = ra[i].x;
                Asn[(kk + 1) * ROW + row] = ra[i].y;
                Asn[(kk + 2) * ROW + row] = ra[i].z;
                Asn[(kk + 3) * ROW + row] = ra[i].w;
                Bsn[(kk + 0) * ROW + row] = rb[i].x;
                Bsn[(kk + 1) * ROW + row] = rb[i].y;
                Bsn[(kk + 2) * ROW + row] = rb[i].z;
                Bsn[(kk + 3) * ROW + row] = rb[i].w;
            }
        }
        __syncthreads();
        cur ^= 1;
    }

    // ---- write logits to smem: [token][expert], row stride ROW ----
#pragma unroll
    for (int i = 0; i < 4; i++) {
        int token = ty * 4 + i;
#pragma unroll
        for (int p = 0; p < 4; p++) {
            float lo, hi;
            unpack2(acc[i][p], lo, hi);
            sm[token * ROW + tx * 8 + 2 * p]     = lo;
            sm[token * ROW + tx * 8 + 2 * p + 1] = hi;
        }
    }
    if (tid < NEXP) cnt[tid] = 0u;
    __syncthreads();

    // ---- per-token softmax + top-2 (one thread per token) ----
    if (tid < BM) {
        float* row = &sm[tid * ROW];
        float mx = row[0];
#pragma unroll
        for (int e = 1; e < NEXP; e++) mx = fmaxf(mx, row[e]);
        float sum = 0.0f;
#pragma unroll
        for (int e = 0; e < NEXP; e++) {
            float p = expf(row[e] - mx);
            row[e] = p;
            sum += p;
        }
        float inv = 1.0f / sum;
        float v1 = -1.0f, v2 = -1.0f;
        int i1 = 0, i2 = 0;
#pragma unroll
        for (int e = 0; e < NEXP; e++) {
            float p = row[e] * inv;
            row[e] = p;                     // softmax score (for aux sums)
            if (p > v1) { v2 = v1; i2 = i1; v1 = p; i1 = e; }
            else if (p > v2) { v2 = p; i2 = e; }
        }
        float tot = v1 + v2 + 1e-20f;
        float s1 = v1 / tot;
        float s2 = v2 / tot;

        int gt = tok0 + tid;
        out[2 * gt + 0] = (float)i1;
        out[2 * gt + 1] = (float)i2;
        out[2 * T_TOK + 2 * gt + 0] = s1;
        out[2 * T_TOK + 2 * gt + 1] = s2;

        atomicAdd(&cnt[i1], 1u);
        atomicAdd(&cnt[i2], 1u);
    }
    __syncthreads();

    // ---- per-expert column sums of softmax scores + count flush ----
    if (tid < NEXP) {
        int e = tid;
        float cs = 0.0f;
#pragma unroll
        for (int t = 0; t < BM; t++) cs += sm[t * ROW + e];
        int b = tok0 / SEQ;
        atomicAdd(&g_score_sum[b * NEXP + e], cs);
        atomicAdd(&g_counts[b * NEXP + e], cnt[e]);
    }
}

__global__ void finalize_aux_kernel(float* __restrict__ out_aux) {
    __shared__ float red[NB * NEXP];
    int i = threadIdx.x;   // 256 threads = NB*NEXP
    float v = (float)g_counts[i] * ((float)NEXP / (float)(SEQ * 2))
              * (g_score_sum[i] / (float)SEQ);
    // reset accumulators for the next graph replay (value already captured in v)
    g_score_sum[i] = 0.0f;
    g_counts[i] = 0u;
    red[i] = v;
    __syncthreads();
    for (int s = (NB * NEXP) / 2; s > 0; s >>= 1) {
        if (i < s) red[i] += red[i + s];
        __syncthreads();
    }
    if (i == 0) out_aux[0] = red[0] * (0.1f / (float)NB);
}

extern "C" void kernel_launch(void* const* d_in, const int* in_sizes, int n_in,
                              void* d_out, int out_size) {
    const float* X = (const float*)d_in[0];   // [4,4096,2048] f32
    const float* W = (const float*)d_in[1];   // [64,2048] f32
    float* out = (float*)d_out;

    moe_gate_kernel<<<T_TOK / BM, NTHREADS>>>(X, W, out);
    finalize_aux_kernel<<<1, 256>>>(out + 4 * T_TOK);
}